// round 5
// baseline (speedup 1.0000x reference)
#include <cuda_runtime.h>
#include <stdint.h>

#define EMB 64
#define HIST 50
#define ROW_F4 (HIST * EMB / 4)   // 800 float4 per output row
#define ENT_F4 (EMB / 4)          // 16 float4 per embedding entry
#define ROWS_PER_BLK 8

// lower_bound(pos, n, key) with an initial guess; exponential (galloping)
// bracket then binary search. For uniform groups the guess is exact: 2 probes.
__device__ __forceinline__ int lower_bound_guess(
    const int* __restrict__ p, int n, int key, int g)
{
    if (g < 0) g = 0;
    if (g > n) g = n;
    int lo, hi;
    if (g < n && __ldg(&p[g]) < key) {
        // answer in (g, n] — gallop right
        int prev = g, step = 1, cur = g + 1;
        while (cur < n && __ldg(&p[cur]) < key) {
            prev = cur; step <<= 1; cur = prev + step;
        }
        lo = prev + 1;
        hi = (cur < n) ? cur : n;
    } else {
        // answer in [0, g] — gallop left
        hi = g;
        int step = 1, cur = g - 1;
        while (cur >= 0 && __ldg(&p[cur]) >= key) {
            hi = cur; step <<= 1; cur = g - step;
        }
        lo = (cur < 0) ? 0 : cur + 1;
    }
    while (lo < hi) {
        int mid = (lo + hi) >> 1;
        if (__ldg(&p[mid]) < key) lo = mid + 1; else hi = mid;
    }
    return lo;
}

__global__ void __launch_bounds__(256) remap_fused_kernel(
    const float4* __restrict__ emb,
    const int*    __restrict__ pos,
    int n_valid, int batch,
    float4* __restrict__ out)
{
    __shared__ int s_start[ROWS_PER_BLK + 1];

    const int b0 = blockIdx.x * ROWS_PER_BLK;
    int nrows = batch - b0;
    if (nrows > ROWS_PER_BLK) nrows = ROWS_PER_BLK;

    const int tid = threadIdx.x;
    if (tid <= nrows) {
        const int key = b0 + tid;
        if (key >= batch) {
            s_start[tid] = n_valid;
        } else {
            const int guess = (int)(((long long)key * n_valid) / batch);
            s_start[tid] = lower_bound_guess(pos, n_valid, key, guess);
        }
    }
    __syncthreads();

    const float4 zero = make_float4(0.f, 0.f, 0.f, 0.f);

    for (int r = 0; r < nrows; r++) {
        const int start = s_start[r];
        int cnt_f4 = (s_start[r + 1] - start) * ENT_F4;
        if (cnt_f4 > ROW_F4) cnt_f4 = ROW_F4;   // mode="drop" clamp

        float4* __restrict__ orow = out + (size_t)(b0 + r) * ROW_F4;
        const float4* __restrict__ irow = emb + (size_t)start * ENT_F4;

        const int v0 = tid;
        const int v1 = tid + 256;
        const int v2 = tid + 512;
        const int v3 = tid + 768;          // only valid for tid < 32

        // front-batch 4 independent loads (MLP=4), then 4 stores
        float4 a0 = (v0 < cnt_f4) ? __ldcs(&irow[v0]) : zero;
        float4 a1 = (v1 < cnt_f4) ? __ldcs(&irow[v1]) : zero;
        float4 a2 = (v2 < cnt_f4) ? __ldcs(&irow[v2]) : zero;
        float4 a3 = (v3 < ROW_F4 && v3 < cnt_f4) ? __ldcs(&irow[v3]) : zero;

        __stcs(&orow[v0], a0);
        __stcs(&orow[v1], a1);
        __stcs(&orow[v2], a2);
        if (v3 < ROW_F4) __stcs(&orow[v3], a3);
    }
}

extern "C" void kernel_launch(void* const* d_in, const int* in_sizes, int n_in,
                              void* d_out, int out_size)
{
    const float4* emb = (const float4*)d_in[0];
    const int*    pos = (const int*)d_in[1];
    const int n_valid = in_sizes[1];
    const int batch   = out_size / (HIST * EMB);

    int cblocks = (batch + ROWS_PER_BLK - 1) / ROWS_PER_BLK;
    remap_fused_kernel<<<cblocks, 256>>>(emb, pos, n_valid, batch, (float4*)d_out);
}

// round 7
// speedup vs baseline: 1.0979x; 1.0979x over previous
#include <cuda_runtime.h>
#include <stdint.h>

#define EMB 64
#define HIST 50
#define ROW_F4 (HIST * EMB / 4)   // 800 float4 per output row
#define ENT_F4 (EMB / 4)          // 16 float4 per embedding entry

// lower_bound(pos, n, key) with guessed fast path.
// Fast path: two INDEPENDENT loads verify the guess in one L2 round-trip.
// Fallback: gallop + binary (arbitrary sorted input stays correct).
__device__ __forceinline__ int lower_bound_guess(
    const int* __restrict__ p, int n, int key, long long num, int den)
{
    int g = (int)(num / den);
    if (g < 0) g = 0;
    if (g > n) g = n;

    // issue both probes up-front (independent)
    int pg   = (g < n) ? __ldg(&p[g])     : 0x7fffffff;
    int pgm1 = (g > 0) ? __ldg(&p[g - 1]) : -0x80000000 + 1;  // -inf sentinel
    if (g == 0) pgm1 = key - 1;                               // always "< key"
    if (pg >= key && pgm1 < key) return g;                    // guess exact

    int lo, hi;
    if (pg < key) {
        // answer in (g, n] — gallop right
        int prev = g, step = 1, cur = g + 1;
        while (cur < n && __ldg(&p[cur]) < key) {
            prev = cur; step <<= 1; cur = prev + step;
        }
        lo = prev + 1;
        hi = (cur < n) ? cur : n;
    } else {
        // answer in [0, g) or == g but pgm1 >= key — gallop left
        hi = g;
        int step = 1, cur = g - 1;
        while (cur >= 0 && __ldg(&p[cur]) >= key) {
            hi = cur; step <<= 1; cur = g - step;
        }
        lo = (cur < 0) ? 0 : cur + 1;
    }
    while (lo < hi) {
        int mid = (lo + hi) >> 1;
        if (__ldg(&p[mid]) < key) lo = mid + 1; else hi = mid;
    }
    return lo;
}

__global__ void __launch_bounds__(256) remap_fused_kernel(
    const float4* __restrict__ emb,
    const int*    __restrict__ pos,
    int n_valid, int batch,
    float4* __restrict__ out)
{
    __shared__ int s_bound[2];

    const int b   = blockIdx.x;
    const int tid = threadIdx.x;

    if (tid < 2) {
        const int key = b + tid;           // b and b+1 resolved concurrently
        s_bound[tid] = lower_bound_guess(pos, n_valid, key,
                                         (long long)key * n_valid, batch);
    }
    __syncthreads();

    const int start = s_bound[0];
    int cnt_f4 = (s_bound[1] - start) * ENT_F4;
    if (cnt_f4 > ROW_F4) cnt_f4 = ROW_F4;  // mode="drop" clamp

    float4* __restrict__ orow = out + (size_t)b * ROW_F4;
    const float4* __restrict__ irow = emb + (size_t)start * ENT_F4;
    const float4 zero = make_float4(0.f, 0.f, 0.f, 0.f);

    const int v0 = tid;
    const int v1 = tid + 256;
    const int v2 = tid + 512;
    const int v3 = tid + 768;              // valid only for tid < 32

    // front-batch 4 independent loads (MLP=4), then 4 stores
    float4 a0 = (v0 < cnt_f4) ? __ldcs(&irow[v0]) : zero;
    float4 a1 = (v1 < cnt_f4) ? __ldcs(&irow[v1]) : zero;
    float4 a2 = (v2 < cnt_f4) ? __ldcs(&irow[v2]) : zero;
    float4 a3 = (v3 < ROW_F4 && v3 < cnt_f4) ? __ldcs(&irow[v3]) : zero;

    __stcs(&orow[v0], a0);
    __stcs(&orow[v1], a1);
    __stcs(&orow[v2], a2);
    if (v3 < ROW_F4) __stcs(&orow[v3], a3);
}

extern "C" void kernel_launch(void* const* d_in, const int* in_sizes, int n_in,
                              void* d_out, int out_size)
{
    const float4* emb = (const float4*)d_in[0];
    const int*    pos = (const int*)d_in[1];
    const int n_valid = in_sizes[1];
    const int batch   = out_size / (HIST * EMB);

    remap_fused_kernel<<<batch, 256>>>(emb, pos, n_valid, batch, (float4*)d_out);
}